// round 17
// baseline (speedup 1.0000x reference)
#include <cuda_runtime.h>
#include <cstdint>
#include <stdint.h>
#include <math.h>

#define Bcnt  2
#define Tlen  2048
#define HIDD  1024
#define NHEAD 16
#define HDIM  64
#define NBH   (Bcnt*NHEAD)   // 32

#define GSTRIDE 136          // smem k-major stride for 128-wide row blocks
#define VSTR    72           // stride for 64-wide blocks (bank = 8*tg+g, conflict-free)

// ---------------- scratch ----------------
__device__ float g_q   [(size_t)Bcnt*Tlen*HIDD];
__device__ float g_k   [(size_t)Bcnt*Tlen*HIDD];
__device__ float g_v   [(size_t)Bcnt*Tlen*HIDD];
__device__ float g_relk[(size_t)Tlen*HIDD];
__device__ float g_ps  [(size_t)NBH*Tlen*Tlen];   // U = (q+bias_v) @ relk^T (unshifted)
__device__ float g_ao  [(size_t)Bcnt*Tlen*HIDD];

// ---------------- tf32 helpers ----------------
__device__ __forceinline__ unsigned f2tf(float f) {
    unsigned u; asm("cvt.rna.tf32.f32 %0, %1;" : "=r"(u) : "f"(f)); return u;
}
__device__ __forceinline__ void mma8(float* c, const unsigned* a, const unsigned* b) {
    asm volatile("mma.sync.aligned.m16n8k8.row.col.f32.tf32.tf32.f32 "
                 "{%0,%1,%2,%3},{%4,%5,%6,%7},{%8,%9},{%0,%1,%2,%3};"
                 : "+f"(c[0]), "+f"(c[1]), "+f"(c[2]), "+f"(c[3])
                 : "r"(a[0]), "r"(a[1]), "r"(a[2]), "r"(a[3]), "r"(b[0]), "r"(b[1]));
}
__device__ __forceinline__ void cp4(unsigned saddr, const float* gptr) {
    asm volatile("cp.async.ca.shared.global [%0], [%1], 4;" :: "r"(saddr), "l"(gptr));
}

// ---------------- double-buffered tf32 GEMM core: C[M,N] = A[M,K] * B[N,K]^T ----------------
__device__ __forceinline__ void gemm_core(const float* __restrict__ A,
                                          const float* __restrict__ B,
                                          float* __restrict__ C,
                                          int M, int N, int K, unsigned* sh) {
    unsigned* sA = sh;                        // [2][16*GSTRIDE]
    unsigned* sB = sh + 2 * 16 * GSTRIDE;     // [2][16*GSTRIDE]
    const int bm = blockIdx.y * 128, bn = blockIdx.x * 128;
    const int tid = threadIdx.x, wid = tid >> 5, lane = tid & 31;
    const int g = lane >> 2, tg = lane & 3;
    const int m0 = (wid & 3) * 32, n0 = (wid >> 2) * 64;
    const int r = tid >> 2, k4 = (tid & 3) * 4;
    float acc[2][8][4] = {};
    float4 pA[2], pB[2];
    const int NC = K / 16;

#pragma unroll
    for (int i = 0; i < 2; i++) {
        int rr = r + 64 * i;
        pA[i] = *(const float4*)&A[(size_t)(bm + rr) * K + k4];
        pB[i] = *(const float4*)&B[(size_t)(bn + rr) * K + k4];
    }
#pragma unroll
    for (int i = 0; i < 2; i++) {
        int rr = r + 64 * i;
        sA[(k4 + 0) * GSTRIDE + rr] = f2tf(pA[i].x);
        sA[(k4 + 1) * GSTRIDE + rr] = f2tf(pA[i].y);
        sA[(k4 + 2) * GSTRIDE + rr] = f2tf(pA[i].z);
        sA[(k4 + 3) * GSTRIDE + rr] = f2tf(pA[i].w);
        sB[(k4 + 0) * GSTRIDE + rr] = f2tf(pB[i].x);
        sB[(k4 + 1) * GSTRIDE + rr] = f2tf(pB[i].y);
        sB[(k4 + 2) * GSTRIDE + rr] = f2tf(pB[i].z);
        sB[(k4 + 3) * GSTRIDE + rr] = f2tf(pB[i].w);
    }
    __syncthreads();

    for (int c = 0; c < NC; c++) {
        unsigned* cA = sA + (c & 1) * 16 * GSTRIDE;
        unsigned* cB = sB + (c & 1) * 16 * GSTRIDE;
        if (c + 1 < NC) {
            int koff = (c + 1) * 16 + k4;
#pragma unroll
            for (int i = 0; i < 2; i++) {
                int rr = r + 64 * i;
                pA[i] = *(const float4*)&A[(size_t)(bm + rr) * K + koff];
                pB[i] = *(const float4*)&B[(size_t)(bn + rr) * K + koff];
            }
        }
#pragma unroll
        for (int ks = 0; ks < 16; ks += 8) {
            unsigned af[2][4], bf[8][2];
#pragma unroll
            for (int mi = 0; mi < 2; mi++) {
                int mb = m0 + mi * 16 + g;
                af[mi][0] = cA[(ks + tg) * GSTRIDE + mb];
                af[mi][1] = cA[(ks + tg) * GSTRIDE + mb + 8];
                af[mi][2] = cA[(ks + tg + 4) * GSTRIDE + mb];
                af[mi][3] = cA[(ks + tg + 4) * GSTRIDE + mb + 8];
            }
#pragma unroll
            for (int ni = 0; ni < 8; ni++) {
                int nb = n0 + ni * 8 + g;
                bf[ni][0] = cB[(ks + tg) * GSTRIDE + nb];
                bf[ni][1] = cB[(ks + tg + 4) * GSTRIDE + nb];
            }
#pragma unroll
            for (int mi = 0; mi < 2; mi++)
#pragma unroll
                for (int ni = 0; ni < 8; ni++) mma8(acc[mi][ni], af[mi], bf[ni]);
        }
        if (c + 1 < NC) {
            unsigned* nA = sA + ((c + 1) & 1) * 16 * GSTRIDE;
            unsigned* nB = sB + ((c + 1) & 1) * 16 * GSTRIDE;
#pragma unroll
            for (int i = 0; i < 2; i++) {
                int rr = r + 64 * i;
                nA[(k4 + 0) * GSTRIDE + rr] = f2tf(pA[i].x);
                nA[(k4 + 1) * GSTRIDE + rr] = f2tf(pA[i].y);
                nA[(k4 + 2) * GSTRIDE + rr] = f2tf(pA[i].z);
                nA[(k4 + 3) * GSTRIDE + rr] = f2tf(pA[i].w);
                nB[(k4 + 0) * GSTRIDE + rr] = f2tf(pB[i].x);
                nB[(k4 + 1) * GSTRIDE + rr] = f2tf(pB[i].y);
                nB[(k4 + 2) * GSTRIDE + rr] = f2tf(pB[i].z);
                nB[(k4 + 3) * GSTRIDE + rr] = f2tf(pB[i].w);
            }
            __syncthreads();
        }
    }
#pragma unroll
    for (int mi = 0; mi < 2; mi++)
#pragma unroll
        for (int ni = 0; ni < 8; ni++) {
            int row = bm + m0 + mi * 16 + g, col = bn + n0 + ni * 8 + 2 * tg;
            *(float2*)&C[(size_t)row * N + col] = make_float2(acc[mi][ni][0], acc[mi][ni][1]);
            *(float2*)&C[(size_t)(row + 8) * N + col] = make_float2(acc[mi][ni][2], acc[mi][ni][3]);
        }
}

// fused projections: z = 0..2 -> q/k/v (M=4096); z = 3 -> relk (M=2048, y<16)
__global__ void __launch_bounds__(256, 2)
gemm_qkvr(const float* __restrict__ x, const float* __restrict__ pos,
          const float* __restrict__ Wq, const float* __restrict__ Wk,
          const float* __restrict__ Wv, const float* __restrict__ Wrel,
          float* __restrict__ q, float* __restrict__ k, float* __restrict__ v,
          float* __restrict__ relk) {
    extern __shared__ unsigned sh[];
    const int z = blockIdx.z;
    if (z == 3) {
        if (blockIdx.y >= Tlen / 128) return;
        gemm_core(pos, Wrel, relk, Tlen, HIDD, HIDD, sh);
        return;
    }
    const float* W = (z == 0) ? Wq : (z == 1) ? Wk : Wv;
    float* C = (z == 0) ? q : (z == 1) ? k : v;
    gemm_core(x, W, C, Bcnt * Tlen, HIDD, HIDD, sh);
}

__global__ void __launch_bounds__(256, 2)
gemm_nt_tc(const float* __restrict__ A, const float* __restrict__ B,
           float* __restrict__ C, int M, int N, int K) {
    extern __shared__ unsigned sh[];
    gemm_core(A, B, C, M, N, K, sh);
}

// ---------------- U[bh,t,l] = sum_d (Q+bias_v) * relk  (tf32, 128x128 tile) ----------------
__global__ void __launch_bounds__(256, 2)
score_tc(const float* __restrict__ Q, const float* __restrict__ Km,
         const float* __restrict__ bias, float* __restrict__ out) {
    extern __shared__ unsigned sh[];
    unsigned* sQ = sh;
    unsigned* sK = sh + 64 * GSTRIDE;
    const int bh = blockIdx.z, b = bh >> 4, h = bh & 15;
    const int t0 = blockIdx.y * 128, l0 = blockIdx.x * 128;
    const float* qb = Q + (size_t)b * Tlen * HIDD + h * HDIM;
    const float* kb = Km + h * HDIM;
    const float* bi = bias + h * HDIM;
    const int tid = threadIdx.x, wid = tid >> 5, lane = tid & 31;
    const int g = lane >> 2, tg = lane & 3;
    const int m0 = (wid & 3) * 32, n0 = (wid >> 2) * 64;
    const int rr = tid >> 4, d4 = (tid & 15) * 4;
    float4 bv = *(const float4*)&bi[d4];
#pragma unroll
    for (int i = 0; i < 8; i++) {
        int r = rr + 16 * i;
        float4 vq = *(const float4*)&qb[(size_t)(t0 + r) * HIDD + d4];
        sQ[(d4 + 0) * GSTRIDE + r] = f2tf(vq.x + bv.x);
        sQ[(d4 + 1) * GSTRIDE + r] = f2tf(vq.y + bv.y);
        sQ[(d4 + 2) * GSTRIDE + r] = f2tf(vq.z + bv.z);
        sQ[(d4 + 3) * GSTRIDE + r] = f2tf(vq.w + bv.w);
        float4 vk = *(const float4*)&kb[(size_t)(l0 + r) * HIDD + d4];
        sK[(d4 + 0) * GSTRIDE + r] = f2tf(vk.x);
        sK[(d4 + 1) * GSTRIDE + r] = f2tf(vk.y);
        sK[(d4 + 2) * GSTRIDE + r] = f2tf(vk.z);
        sK[(d4 + 3) * GSTRIDE + r] = f2tf(vk.w);
    }
    __syncthreads();
    float acc[2][8][4] = {};
#pragma unroll
    for (int ks = 0; ks < 64; ks += 8) {
        unsigned af[2][4], bf[8][2];
#pragma unroll
        for (int mi = 0; mi < 2; mi++) {
            int mb = m0 + mi * 16 + g;
            af[mi][0] = sQ[(ks + tg) * GSTRIDE + mb];
            af[mi][1] = sQ[(ks + tg) * GSTRIDE + mb + 8];
            af[mi][2] = sQ[(ks + tg + 4) * GSTRIDE + mb];
            af[mi][3] = sQ[(ks + tg + 4) * GSTRIDE + mb + 8];
        }
#pragma unroll
        for (int ni = 0; ni < 8; ni++) {
            int nb = n0 + ni * 8 + g;
            bf[ni][0] = sK[(ks + tg) * GSTRIDE + nb];
            bf[ni][1] = sK[(ks + tg + 4) * GSTRIDE + nb];
        }
#pragma unroll
        for (int mi = 0; mi < 2; mi++)
#pragma unroll
            for (int ni = 0; ni < 8; ni++) mma8(acc[mi][ni], af[mi], bf[ni]);
    }
    float* ob = out + (size_t)bh * Tlen * Tlen;
#pragma unroll
    for (int mi = 0; mi < 2; mi++)
#pragma unroll
        for (int ni = 0; ni < 8; ni++) {
            int row = t0 + m0 + mi * 16 + g, col = l0 + n0 + ni * 8 + 2 * tg;
            *(float2*)&ob[(size_t)row * Tlen + col] = make_float2(acc[mi][ni][0], acc[mi][ni][1]);
            *(float2*)&ob[(size_t)(row + 8) * Tlen + col] = make_float2(acc[mi][ni][2], acc[mi][ni][3]);
        }
}

// ---------------- fused flash attention (j-tile = 64, smem ~104KB, 2 CTA/SM) ----------------
// No online max. U gather prefetched via cp.async (4B) into the sP slots each
// thread later overwrites with P — zero register cost, latency hidden behind
// K/V staging + S-MMA. Loop-top __syncthreads orders it against the previous
// iteration's PV reads of sP.
__global__ void __launch_bounds__(256, 2)
flash_tc(const float* __restrict__ Q, const float* __restrict__ K,
         const float* __restrict__ V, const float* __restrict__ U,
         const float* __restrict__ bias_u, float* __restrict__ O) {
    extern __shared__ unsigned sh[];
    unsigned* sQ = sh;                       // [d=64][GSTRIDE]    34816 B
    unsigned* sK = sQ + 64 * GSTRIDE;        // [d=64][VSTR]       18432 B
    unsigned* sV = sK + 64 * VSTR;           // [s=64][VSTR]       18432 B
    unsigned* sP = sV + 64 * VSTR;           // [s=64][GSTRIDE]    34816 B
    const unsigned sP_base = (unsigned)__cvta_generic_to_shared(sP);
    const int bh = blockIdx.y, b = bh >> 4, h = bh & 15;
    const int t0 = blockIdx.x * 128;
    const float* qb = Q + (size_t)b * Tlen * HIDD + h * HDIM;
    const float* kb = K + (size_t)b * Tlen * HIDD + h * HDIM;
    const float* vb = V + (size_t)b * Tlen * HIDD + h * HDIM;
    const float* ub = U + (size_t)bh * Tlen * Tlen;
    const float* bi = bias_u + h * HDIM;
    const int tid = threadIdx.x, wid = tid >> 5, lane = tid & 31;
    const int g = lane >> 2, tg = lane & 3;
    const int m0 = wid * 16;
    const int rr = tid >> 4, d4 = (tid & 15) * 4;

    // stage Q (+bias_u), k-major tf32 (128 rows x d=64)
    {
        float4 bv = *(const float4*)&bi[d4];
#pragma unroll
        for (int i = 0; i < 8; i++) {
            int r = rr + 16 * i;
            float4 vq = *(const float4*)&qb[(size_t)(t0 + r) * HIDD + d4];
            sQ[(d4 + 0) * GSTRIDE + r] = f2tf(vq.x + bv.x);
            sQ[(d4 + 1) * GSTRIDE + r] = f2tf(vq.y + bv.y);
            sQ[(d4 + 2) * GSTRIDE + r] = f2tf(vq.z + bv.z);
            sQ[(d4 + 3) * GSTRIDE + r] = f2tf(vq.w + bv.w);
        }
    }

    float oacc[8][4] = {};
    float lpart[2] = {0.0f, 0.0f};
    const int trow0 = t0 + m0 + g;       // this thread's query rows: trow0, trow0+8

    for (int j0 = 0; j0 < Tlen; j0 += 64) {
        __syncthreads();   // previous iteration's mma/LDS of sK/sV/sP done

        // prefetch rel-shifted U entries into this thread's future P slots (async)
#pragma unroll
        for (int ni = 0; ni < 8; ni++)
#pragma unroll
            for (int c = 0; c < 4; c++) {
                int t = trow0 + (c >= 2 ? 8 : 0);
                int j = j0 + ni * 8 + 2 * tg + (c & 1);
                int slot = (ni * 8 + 2 * tg + (c & 1)) * GSTRIDE + m0 + g + (c >= 2 ? 8 : 0);
                unsigned saddr = sP_base + ((unsigned)slot << 2);
                if (j <= t)          cp4(saddr, &ub[(size_t)t * Tlen + (Tlen - 1 - t + j)]);
                else if (j == t + 1) sP[slot] = 0u;
                else                 cp4(saddr, &ub[(size_t)(t + 1) * Tlen + (j - t - 2)]);
            }
        asm volatile("cp.async.commit_group;");

        // stage K tile [64 rows][d 64] k-major, V tile [s 64][d 64]
#pragma unroll
        for (int i = 0; i < 4; i++) {
            int r = rr + 16 * i;
            float4 vk = *(const float4*)&kb[(size_t)(j0 + r) * HIDD + d4];
            sK[(d4 + 0) * VSTR + r] = f2tf(vk.x);
            sK[(d4 + 1) * VSTR + r] = f2tf(vk.y);
            sK[(d4 + 2) * VSTR + r] = f2tf(vk.z);
            sK[(d4 + 3) * VSTR + r] = f2tf(vk.w);
            float4 vv = *(const float4*)&vb[(size_t)(j0 + r) * HIDD + d4];
            sV[r * VSTR + d4 + 0] = f2tf(vv.x);
            sV[r * VSTR + d4 + 1] = f2tf(vv.y);
            sV[r * VSTR + d4 + 2] = f2tf(vv.z);
            sV[r * VSTR + d4 + 3] = f2tf(vv.w);
        }
        __syncthreads();

        // S = Qu @ K^T  (warp: 16 rows x 64 cols) — overlaps the U cp.async
        float sacc[8][4] = {};
#pragma unroll
        for (int ks = 0; ks < 64; ks += 8) {
            unsigned af[4], bf[8][2];
            int mb = m0 + g;
            af[0] = sQ[(ks + tg) * GSTRIDE + mb];
            af[1] = sQ[(ks + tg) * GSTRIDE + mb + 8];
            af[2] = sQ[(ks + tg + 4) * GSTRIDE + mb];
            af[3] = sQ[(ks + tg + 4) * GSTRIDE + mb + 8];
#pragma unroll
            for (int ni = 0; ni < 8; ni++) {
                int nb = ni * 8 + g;
                bf[ni][0] = sK[(ks + tg) * VSTR + nb];
                bf[ni][1] = sK[(ks + tg + 4) * VSTR + nb];
            }
#pragma unroll
            for (int ni = 0; ni < 8; ni++) mma8(sacc[ni], af, bf[ni]);
        }

        asm volatile("cp.async.wait_group 0;");   // own slots only; no barrier needed

        // P = exp((S + U) * scale); overwrite slots with P; accumulate row sums
#pragma unroll
        for (int ni = 0; ni < 8; ni++) {
            int s0i = (ni * 8 + 2 * tg + 0) * GSTRIDE + m0 + g;
            int s1i = (ni * 8 + 2 * tg + 1) * GSTRIDE + m0 + g;
            float u0 = __uint_as_float(sP[s0i]);
            float u1 = __uint_as_float(sP[s1i]);
            float u2 = __uint_as_float(sP[s0i + 8]);
            float u3 = __uint_as_float(sP[s1i + 8]);
            float p0 = __expf((sacc[ni][0] + u0) * 0.125f);
            float p1 = __expf((sacc[ni][1] + u1) * 0.125f);
            float p2 = __expf((sacc[ni][2] + u2) * 0.125f);
            float p3 = __expf((sacc[ni][3] + u3) * 0.125f);
            lpart[0] += p0 + p1;
            lpart[1] += p2 + p3;
            sP[s0i]     = f2tf(p0);
            sP[s1i]     = f2tf(p1);
            sP[s0i + 8] = f2tf(p2);
            sP[s1i + 8] = f2tf(p3);
        }
        __syncwarp();   // sP columns are warp-private; lanes exchange within warp

        // O += P @ V  (k = 64 over s)
#pragma unroll
        for (int ks = 0; ks < 64; ks += 8) {
            unsigned af[4], bf[8][2];
            int mb = m0 + g;
            af[0] = sP[(ks + tg) * GSTRIDE + mb];
            af[1] = sP[(ks + tg) * GSTRIDE + mb + 8];
            af[2] = sP[(ks + tg + 4) * GSTRIDE + mb];
            af[3] = sP[(ks + tg + 4) * GSTRIDE + mb + 8];
#pragma unroll
            for (int ni = 0; ni < 8; ni++) {
                int nb = ni * 8 + g;
                bf[ni][0] = sV[(ks + tg) * VSTR + nb];
                bf[ni][1] = sV[(ks + tg + 4) * VSTR + nb];
            }
#pragma unroll
            for (int ni = 0; ni < 8; ni++) mma8(oacc[ni], af, bf[ni]);
        }
    }

    // final cross-lane row-sum reduction, normalize, write out
#pragma unroll
    for (int st = 1; st <= 2; st <<= 1) {
        lpart[0] += __shfl_xor_sync(0xffffffffu, lpart[0], st);
        lpart[1] += __shfl_xor_sync(0xffffffffu, lpart[1], st);
    }
    float inv0 = 1.0f / lpart[0], inv1 = 1.0f / lpart[1];
    float* ob = O + (size_t)b * Tlen * HIDD + h * HDIM;
#pragma unroll
    for (int ni = 0; ni < 8; ni++) {
        int row = t0 + m0 + g, col = ni * 8 + 2 * tg;
        *(float2*)&ob[(size_t)row * HIDD + col] =
            make_float2(oacc[ni][0] * inv0, oacc[ni][1] * inv0);
        *(float2*)&ob[(size_t)(row + 8) * HIDD + col] =
            make_float2(oacc[ni][2] * inv1, oacc[ni][3] * inv1);
    }
}

// ---------------- launch ----------------
extern "C" void kernel_launch(void* const* d_in, const int* in_sizes, int n_in,
                              void* d_out, int out_size) {
    const float* x    = (const float*)d_in[0];
    const float* pos  = (const float*)d_in[1];
    const float* Wq   = (const float*)d_in[2];
    const float* Wk   = (const float*)d_in[3];
    const float* Wv   = (const float*)d_in[4];
    const float* Wo   = (const float*)d_in[5];
    const float* Wrel = (const float*)d_in[6];
    const float* bu   = (const float*)d_in[7];
    const float* bv   = (const float*)d_in[8];
    float* out = (float*)d_out;

    float *q, *k, *v, *relk, *ps, *ao;
    cudaGetSymbolAddress((void**)&q,    g_q);
    cudaGetSymbolAddress((void**)&k,    g_k);
    cudaGetSymbolAddress((void**)&v,    g_v);
    cudaGetSymbolAddress((void**)&relk, g_relk);
    cudaGetSymbolAddress((void**)&ps,   g_ps);
    cudaGetSymbolAddress((void**)&ao,   g_ao);

    const int M  = Bcnt * Tlen;   // 4096
    const int Np = HIDD;          // 1024
    const int Kp = HIDD;          // 1024

    const int GM_SMEM = 4 * 16 * GSTRIDE * 4;                              // 69632
    const int SC_SMEM = 2 * 64 * GSTRIDE * 4;                              // 69632
    const int FL_SMEM = (64 * GSTRIDE + 64 * VSTR + 64 * VSTR + 64 * GSTRIDE) * 4; // 106496
    cudaFuncSetAttribute(gemm_qkvr,  cudaFuncAttributeMaxDynamicSharedMemorySize, GM_SMEM);
    cudaFuncSetAttribute(gemm_nt_tc, cudaFuncAttributeMaxDynamicSharedMemorySize, GM_SMEM);
    cudaFuncSetAttribute(score_tc,   cudaFuncAttributeMaxDynamicSharedMemorySize, SC_SMEM);
    cudaFuncSetAttribute(flash_tc,   cudaFuncAttributeMaxDynamicSharedMemorySize, FL_SMEM);

    dim3 gQKVR(Np / 128, M / 128, 4);    // (8, 32, 4); z=3 uses y<16 only
    gemm_qkvr<<<gQKVR, 256, GM_SMEM>>>(x, pos, Wq, Wk, Wv, Wrel, q, k, v, relk);

    dim3 gScore(Tlen / 128, Tlen / 128, NBH);   // (16, 16, 32)
    score_tc<<<gScore, 256, SC_SMEM>>>(q, relk, bv, ps);

    dim3 gFlash(Tlen / 128, NBH);               // (16, 32)
    flash_tc<<<gFlash, 256, FL_SMEM>>>(q, k, v, ps, bu, ao);

    dim3 gProj(Np / 128, M / 128);              // (8, 32)
    gemm_nt_tc<<<gProj, 256, GM_SMEM>>>(ao, Wo, out, M, Np, Kp);
}